// round 16
// baseline (speedup 1.0000x reference)
#include <cuda_runtime.h>
#include <cuda_fp16.h>
#include <cstdint>
#include <math.h>

// Problem constants
#define BATCH 8
#define CIN   256
#define COUT  256
#define HH    64
#define WW    64
#define K2    9
#define NCHUNK 72          // 9 taps * 8 c-chunks of 32

// ---------------- scratch (__device__ globals; no allocation) ----------------
__device__ __half g_xh[BATCH * HH * WW * CIN];       // NHWC x, fp16 (16 MB) — all gathers
__device__ __half g_wtB[NCHUNK * 8192];              // fp16 fragment-ordered main B tiles (1.125 MB)
__device__ __half g_wtOM[NCHUNK * 1024];             // fp16 fragment-ordered offmask B tiles (147 KB)
__device__ float  g_offmask[BATCH * HH * WW * 32];   // 18 off, 9 mask per pixel (fp32)

// ---------------- helpers ----------------
__device__ __forceinline__ uint32_t smem_u32(const void* p) {
    uint32_t a;
    asm("{ .reg .u64 t; cvta.to.shared.u64 t, %1; cvt.u32.u64 %0, t; }" : "=r"(a) : "l"(p));
    return a;
}
__device__ __forceinline__ void cp_async16(uint32_t s, const void* g) {
    asm volatile("cp.async.cg.shared.global [%0], [%1], 16;" :: "r"(s), "l"(g) : "memory");
}
__device__ __forceinline__ void cp_commit() { asm volatile("cp.async.commit_group;" ::: "memory"); }
__device__ __forceinline__ void cp_wait0()  { asm volatile("cp.async.wait_group 0;" ::: "memory"); }

__device__ __forceinline__ void mma_f16(float4& d, const uint4& a, const uint2& b) {
    asm volatile(
        "mma.sync.aligned.m16n8k16.row.col.f32.f16.f16.f32 "
        "{%0,%1,%2,%3}, {%4,%5,%6,%7}, {%8,%9}, {%0,%1,%2,%3};"
        : "+f"(d.x), "+f"(d.y), "+f"(d.z), "+f"(d.w)
        : "r"(a.x), "r"(a.y), "r"(a.z), "r"(a.w), "r"(b.x), "r"(b.y));
}

// ---------------- kernel 1: NCHW fp32 -> NHWC fp16 transpose ----------------
__global__ void transpose_x_kernel(const float* __restrict__ x)
{
    __shared__ float tile[32][33];
    int bh = blockIdx.z;
    int b = bh >> 6, h = bh & 63;
    int wbase = blockIdx.x * 32;
    int cbase = blockIdx.y * 32;
    int tx = threadIdx.x, ty = threadIdx.y;

    int wi = wbase + tx;
#pragma unroll
    for (int j = 0; j < 4; j++) {
        int c = cbase + ty + j * 8;
        tile[ty + j * 8][tx] = x[((b * CIN + c) * HH + h) * WW + wi];
    }
    __syncthreads();
    int c2 = cbase + tx;
#pragma unroll
    for (int j = 0; j < 4; j++) {
        int w2 = wbase + ty + j * 8;
        float v = tile[tx][ty + j * 8];
        g_xh[((bh) * WW + w2) * CIN + c2] = __float2half_rn(v);
    }
}

// ---------------- kernel 2: pack main weight into fp16 fragment-ordered B tiles ----------------
__global__ void pack_wtB_kernel(const float* __restrict__ weight)
{
    int i = blockIdx.x * blockDim.x + threadIdx.x;
    if (i >= NCHUNK * 4096) return;
    int q = i >> 12;
    int w = i & 4095;
    int r = w & 1;
    int lane = (w >> 1) & 31;
    int ks = (w >> 6) & 1;
    int n_blk = (w >> 7) & 31;
    int tap = q >> 3;
    int n = n_blk * 8 + (lane >> 2);
    int c = (q & 7) * 32 + ks * 16 + (lane & 3) * 2 + r * 8;
    float v0 = weight[(n * CIN + c) * K2 + tap];
    float v1 = weight[(n * CIN + c + 1) * K2 + tap];
    ((__half2*)g_wtB)[i] = __floats2half2_rn(v0, v1);
}

// ---------------- kernel 2b: pack offset+mask weights into fp16 B tiles (N=32 padded) ----------------
__global__ void pack_wtOM_kernel(const float* __restrict__ offset_w,
                                 const float* __restrict__ mod_w)
{
    int i = blockIdx.x * blockDim.x + threadIdx.x;
    if (i >= NCHUNK * 512) return;
    int q = i >> 9;
    int w = i & 511;
    int r = w & 1;
    int lane = (w >> 1) & 31;
    int ks = (w >> 6) & 1;
    int n_blk = (w >> 7) & 3;
    int tap = q >> 3;
    int n = n_blk * 8 + (lane >> 2);
    int c = (q & 7) * 32 + ks * 16 + (lane & 3) * 2 + r * 8;
    float v0 = 0.f, v1 = 0.f;
    if (n < 18)      { v0 = offset_w[(n * CIN + c) * K2 + tap]; v1 = offset_w[(n * CIN + c + 1) * K2 + tap]; }
    else if (n < 27) { v0 = mod_w[((n - 18) * CIN + c) * K2 + tap]; v1 = mod_w[((n - 18) * CIN + c + 1) * K2 + tap]; }
    ((__half2*)g_wtOM)[i] = __floats2half2_rn(v0, v1);
}

// ---------------- kernel 3: offset/mask conv via fp16 mma — M=256 (4 rows) per block ----------------
// Block = 4 rows: M=256 px, N=32, K=2304 in 72 chunks. 256 threads = 8 warps (8M x 1N).
// Each warp: 2 m_blks x 4 n8 x 2 ks = 16 MMAs per chunk. Distance-2 A pipeline.
__global__ __launch_bounds__(256) void offmask_mma_kernel(const float* __restrict__ offset_b,
                                                          const float* __restrict__ mod_b)
{
    __shared__ __align__(16) char smA[2][16384];  // A frag: [m_blk16][ks16 2][lane32][16B]
    __shared__ __align__(16) char smB[2][2048];   // B frag: [n_blk4][ks16 2][lane32][8B]

    int t = threadIdx.x;
    int wid = t >> 5, lane = t & 31;
    int bid = blockIdx.x;
    int b = bid >> 4, h0 = (bid & 15) << 2;

    uint32_t sbB[2] = { smem_u32(smB[0]), smem_u32(smB[1]) };

    // staging identity: pixel p_ = t (0..255), 32 channels per chunk
    int p_ = t;
    int m_blk = p_ >> 4, rr = p_ & 15, rA = rr & 7, r8 = rr >> 3;

    float4 acc[2][4];
#pragma unroll
    for (int mi = 0; mi < 2; mi++)
#pragma unroll
        for (int ni = 0; ni < 4; ni++) acc[mi][ni] = make_float4(0.f, 0.f, 0.f, 0.f);

    uint4 ga[4];   // 32 fp16 channels — loaded one FULL iteration before STS

    auto loadA = [&](int q) {
        int tap = q >> 3;
        int ki = tap / 3, kj = tap - ki * 3;
        int y = h0 + (p_ >> 6) + ki - 1;
        int xc = (p_ & 63) + kj - 1;
        if ((unsigned)y < 64u && (unsigned)xc < 64u) {
            const uint4* src = (const uint4*)&g_xh[(((b * HH + y) * WW + xc) * CIN) + (q & 7) * 32];
#pragma unroll
            for (int j = 0; j < 4; j++) ga[j] = src[j];
        } else {
#pragma unroll
            for (int j = 0; j < 4; j++) ga[j] = make_uint4(0, 0, 0, 0);
        }
    };
    // thread covers all four former q4 roles: q4 = s*2 + j2, channels q4*8..+7
    auto stsA = [&](int buf) {
        __half2* Aw = (__half2*)smA[buf];
#pragma unroll
        for (int q4 = 0; q4 < 4; q4++) {
            int s  = q4 >> 1;
            int j2 = q4 & 1;
            int base = ((m_blk * 2 + s) * 32 + 4 * rA) * 4 + r8 + 2 * j2;
            const __half2* v = (const __half2*)&ga[q4];
            Aw[base + 0 * 4] = v[0];
            Aw[base + 1 * 4] = v[1];
            Aw[base + 2 * 4] = v[2];
            Aw[base + 3 * 4] = v[3];
        }
    };

    // prologue: stage chunk 0 into buffer 0; preload chunk 1 into registers
    loadA(0);
    stsA(0);
    loadA(1);
    if (t < 128) cp_async16(sbB[0] + t * 16, (const char*)g_wtOM + t * 16);
    cp_commit();
    cp_wait0();
    __syncthreads();

    for (int q = 0; q < NCHUNK; q++) {
        int buf = q & 1, nbuf = buf ^ 1;
        bool pre = (q + 1 < NCHUNK);
        if (pre) {
            if (t < 128) cp_async16(sbB[nbuf] + t * 16, (const char*)g_wtOM + (size_t)(q + 1) * 2048 + t * 16);
            cp_commit();
        }

        const uint4* As = (const uint4*)smA[buf];
        const uint2* Bs = (const uint2*)smB[buf];
#pragma unroll
        for (int ks = 0; ks < 2; ks++) {
            uint4 a0 = As[((wid * 2 + 0) * 2 + ks) * 32 + lane];
            uint4 a1 = As[((wid * 2 + 1) * 2 + ks) * 32 + lane];
#pragma unroll
            for (int ni = 0; ni < 4; ni++) {
                uint2 bf = Bs[(ni * 2 + ks) * 32 + lane];
                mma_f16(acc[0][ni], a0, bf);
                mma_f16(acc[1][ni], a1, bf);
            }
        }

        if (pre) stsA(nbuf);               // ga holds chunk q+1 (loaded at iter q-1) — no stall
        if (q + 2 < NCHUNK) loadA(q + 2);  // refill ga for next iteration
        cp_wait0();
        __syncthreads();
    }

    // epilogue: bias + sigmoid(mask), store fp32
#pragma unroll
    for (int mi = 0; mi < 2; mi++) {
        int mt = wid * 2 + mi;
#pragma unroll
        for (int ni = 0; ni < 4; ni++) {
            const float* a4 = (const float*)&acc[mi][ni];
#pragma unroll
            for (int rr2 = 0; rr2 < 2; rr2++) {
                int px = mt * 16 + (lane >> 2) + rr2 * 8;
                int h = h0 + (px >> 6), w = px & 63;
#pragma unroll
                for (int cc = 0; cc < 2; cc++) {
                    int n = ni * 8 + (lane & 3) * 2 + cc;
                    if (n >= 27) continue;
                    float v = a4[rr2 * 2 + cc];
                    if (n < 18) v += offset_b[n];
                    else        v = 2.f / (1.f + expf(-(v + mod_b[n - 18])));
                    g_offmask[(((b * HH + h) * WW) + w) * 32 + n] = v;
                }
            }
        }
    }
}

// ---------------- kernel 4: deformable conv via fp16 mma (R13 distance-1 staging) ----------------
// Block = 2 rows: M=128 px, N=256, K=2304 in 72 chunks of 32. 512 threads = 16 warps (4M x 4N).
#define SM_MIDX   0
#define SM_MWGT   18432
#define SM_A0     36864
#define SM_A1     45056
#define SM_B0     53248
#define SM_B1     69632
#define SM_BIAS   86016
#define SM_TOTAL  87040

__global__ __launch_bounds__(512) void deform_mma_kernel(const float* __restrict__ bias,
                                                         float* __restrict__ out)
{
    extern __shared__ char smem[];
    uint32_t sb = smem_u32(smem);
    int t = threadIdx.x;
    int bid = blockIdx.x;
    int b = bid >> 5, h0 = (bid & 31) << 1;

    int4*   midx  = (int4*)(smem + SM_MIDX);
    float4* mwgt  = (float4*)(smem + SM_MWGT);
    float*  biasS = (float*)(smem + SM_BIAS);

    if (t < 256) biasS[t] = bias[t];

    // ---- per-block sampling metadata: 128 px x 9 taps ----
    for (int e = t; e < 128 * K2; e += 512) {
        int p = e / K2;
        int k = e - p * K2;
        int r = p >> 6, w = p & 63;
        int h = h0 + r;
        const float* om = &g_offmask[(((b * HH + h) * WW) + w) * 32];
        float dy = om[2 * k];
        float dx = om[2 * k + 1];
        float m  = om[18 + k];
        int ki = k / 3, kj = k - ki * 3;
        float py = dy + (float)(h - 1 + ki);
        float px = dx + (float)(w - 1 + kj);
        float y0f = floorf(py), x0f = floorf(px);
        float ly = py - y0f, lx = px - x0f;
        int y0 = (int)y0f, x0 = (int)x0f;
        int y1 = y0 + 1, x1 = x0 + 1;
        float wy0 = 1.f - ly, wx0 = 1.f - lx;
        bool vy0 = (y0 >= 0) && (y0 < HH);
        bool vy1 = (y1 >= 0) && (y1 < HH);
        bool vx0 = (x0 >= 0) && (x0 < WW);
        bool vx1 = (x1 >= 0) && (x1 < WW);
        float w00 = (vy0 && vx0) ? wy0 * wx0 * m : 0.f;
        float w01 = (vy0 && vx1) ? wy0 * lx  * m : 0.f;
        float w10 = (vy1 && vx0) ? ly  * wx0 * m : 0.f;
        float w11 = (vy1 && vx1) ? ly  * lx  * m : 0.f;
        int y0c = min(max(y0, 0), HH - 1);
        int y1c = min(max(y1, 0), HH - 1);
        int x0c = min(max(x0, 0), WW - 1);
        int x1c = min(max(x1, 0), WW - 1);
        midx[e] = make_int4(((b * HH + y0c) * WW + x0c) * CIN,
                            ((b * HH + y0c) * WW + x1c) * CIN,
                            ((b * HH + y1c) * WW + x0c) * CIN,
                            ((b * HH + y1c) * WW + x1c) * CIN);
        mwgt[e] = make_float4(w00, w01, w10, w11);
    }
    __syncthreads();

    // staging identity: pixel p_=t>>2, channels q4*8..+7 of chunk
    int p_ = t >> 2, q4 = t & 3;
    int m_blk = p_ >> 4, rr = p_ & 15, rA = rr & 7, r8 = rr >> 3;
    int jw = r8 + 2 * (q4 & 1);
    int ks16s = q4 >> 1;
    int stsBase = ((m_blk * 2 + ks16s) * 32 + 4 * rA) * 4 + jw;   // half2-word index in A tile

    int wid = t >> 5, lane = t & 31;
    int wm = wid & 3, wn = wid >> 2;

    float4 acc[2][8];
#pragma unroll
    for (int mi = 0; mi < 2; mi++)
#pragma unroll
        for (int ni = 0; ni < 8; ni++) acc[mi][ni] = make_float4(0.f, 0.f, 0.f, 0.f);

    char* Abuf[2] = { smem + SM_A0, smem + SM_A1 };
    char* Bbuf[2] = { smem + SM_B0, smem + SM_B1 };
    uint32_t BbufU[2] = { sb + SM_B0, sb + SM_B1 };

    uint4 c00, c01, c10, c11;   // 4 corners x 8 fp16 channels
    int4 id;                    // corner base indices — persist across the 8 c-chunks of a tap
    float4 wg;                  // corner weights — same

    auto loadCorners = [&](int qq) {
        int cb = ((qq & 7) << 5) + q4 * 8;
        c00 = *(const uint4*)&g_xh[id.x + cb];
        c01 = *(const uint4*)&g_xh[id.y + cb];
        c10 = *(const uint4*)&g_xh[id.z + cb];
        c11 = *(const uint4*)&g_xh[id.w + cb];
    };
    auto stsA = [&](int buf) {
        __half2* Aw = (__half2*)Abuf[buf];
        const __half2* a0 = (const __half2*)&c00;
        const __half2* a1 = (const __half2*)&c01;
        const __half2* a2 = (const __half2*)&c10;
        const __half2* a3 = (const __half2*)&c11;
#pragma unroll
        for (int ci = 0; ci < 4; ci++) {
            float2 f0 = __half22float2(a0[ci]);
            float2 f1 = __half22float2(a1[ci]);
            float2 f2 = __half22float2(a2[ci]);
            float2 f3 = __half22float2(a3[ci]);
            float sx = wg.x * f0.x + wg.y * f1.x + wg.z * f2.x + wg.w * f3.x;
            float sy = wg.x * f0.y + wg.y * f1.y + wg.z * f2.y + wg.w * f3.y;
            Aw[stsBase + ci * 4] = __floats2half2_rn(sx, sy);
        }
    };

    // prologue: stage chunk 0 (tap 0)
    {
        id = midx[p_ * K2 + 0];
        wg = mwgt[p_ * K2 + 0];
        loadCorners(0);
#pragma unroll
        for (int i = 0; i < 2; i++)
            cp_async16(BbufU[0] + t * 16 + i * 8192, (const char*)g_wtB + t * 16 + i * 8192);
        cp_commit();
        stsA(0);
        cp_wait0();
        __syncthreads();
    }

    for (int q = 0; q < NCHUNK; q++) {
        int buf = q & 1, nbuf = buf ^ 1;
        bool pre = (q + 1 < NCHUNK);

        if (pre) {
            int qq = q + 1;
            if ((qq & 7) == 0) {            // tap boundary: refresh metadata
                int tap = qq >> 3;
                id = midx[p_ * K2 + tap];
                wg = mwgt[p_ * K2 + tap];
            }
            loadCorners(qq);
            const char* bsrc = (const char*)g_wtB + (size_t)qq * 16384;
#pragma unroll
            for (int i = 0; i < 2; i++)
                cp_async16(BbufU[nbuf] + t * 16 + i * 8192, bsrc + t * 16 + i * 8192);
            cp_commit();
        }

        const uint4* As = (const uint4*)Abuf[buf];
        const uint2* Bs = (const uint2*)Bbuf[buf];

        // ks = 0
        {
            uint4 a0 = As[((wm * 2 + 0) * 2 + 0) * 32 + lane];
            uint4 a1 = As[((wm * 2 + 1) * 2 + 0) * 32 + lane];
#pragma unroll
            for (int ni = 0; ni < 8; ni++) {
                uint2 bf = Bs[((wn * 8 + ni) * 2 + 0) * 32 + lane];
                mma_f16(acc[0][ni], a0, bf);
                mma_f16(acc[1][ni], a1, bf);
            }
        }

        // convert + STS A for q+1 (overlap with MMA)
        if (pre) stsA(nbuf);

        // ks = 1
        {
            uint4 a0 = As[((wm * 2 + 0) * 2 + 1) * 32 + lane];
            uint4 a1 = As[((wm * 2 + 1) * 2 + 1) * 32 + lane];
#pragma unroll
            for (int ni = 0; ni < 8; ni++) {
                uint2 bf = Bs[((wn * 8 + ni) * 2 + 1) * 32 + lane];
                mma_f16(acc[0][ni], a0, bf);
                mma_f16(acc[1][ni], a1, bf);
            }
        }

        cp_wait0();
        __syncthreads();
    }

    // ---- epilogue: bias + scattered NCHW stores ----
    int gid = lane >> 2, tig = lane & 3;
#pragma unroll
    for (int mi = 0; mi < 2; mi++) {
        int p0 = wm * 32 + mi * 16 + gid;
        int p1 = p0 + 8;
        int h_0 = h0 + (p0 >> 6), w_0 = p0 & 63;
        int h_1 = h0 + (p1 >> 6), w_1 = p1 & 63;
#pragma unroll
        for (int ni = 0; ni < 8; ni++) {
            int o0 = wn * 64 + ni * 8 + tig * 2;
            int o1 = o0 + 1;
            float4 d = acc[mi][ni];
            out[((b * COUT + o0) * HH + h_0) * WW + w_0] = d.x + biasS[o0];
            out[((b * COUT + o1) * HH + h_0) * WW + w_0] = d.y + biasS[o1];
            out[((b * COUT + o0) * HH + h_1) * WW + w_1] = d.z + biasS[o0];
            out[((b * COUT + o1) * HH + h_1) * WW + w_1] = d.w + biasS[o1];
        }
    }
}

// ---------------- launcher ----------------
extern "C" void kernel_launch(void* const* d_in, const int* in_sizes, int n_in,
                              void* d_out, int out_size)
{
    const float* x        = (const float*)d_in[0];
    const float* offset_w = (const float*)d_in[1];
    const float* offset_b = (const float*)d_in[2];
    const float* mod_w    = (const float*)d_in[3];
    const float* mod_b    = (const float*)d_in[4];
    const float* weight   = (const float*)d_in[5];
    const float* bias     = (const float*)d_in[6];
    float* out = (float*)d_out;

    cudaFuncSetAttribute(deform_mma_kernel, cudaFuncAttributeMaxDynamicSharedMemorySize, SM_TOTAL);

    transpose_x_kernel<<<dim3(2, 8, BATCH * HH), dim3(32, 8)>>>(x);
    pack_wtB_kernel<<<(NCHUNK * 4096 + 255) / 256, 256>>>(weight);
    pack_wtOM_kernel<<<(NCHUNK * 512 + 255) / 256, 256>>>(offset_w, mod_w);
    offmask_mma_kernel<<<BATCH * HH / 4, 256>>>(offset_b, mod_b);
    deform_mma_kernel<<<BATCH * HH / 2, 512, SM_TOTAL>>>(bias, out);
}

// round 17
// speedup vs baseline: 1.0548x; 1.0548x over previous
#include <cuda_runtime.h>
#include <cuda_fp16.h>
#include <cstdint>
#include <math.h>

// Problem constants
#define BATCH 8
#define CIN   256
#define COUT  256
#define HH    64
#define WW    64
#define K2    9
#define NCHUNK 72          // 9 taps * 8 c-chunks of 32

// ---------------- scratch (__device__ globals; no allocation) ----------------
__device__ __half g_xh[BATCH * HH * WW * CIN];       // NHWC x, fp16 (16 MB) — all gathers
__device__ __half g_wtB[NCHUNK * 8192];              // fp16 fragment-ordered main B tiles (1.125 MB)
__device__ __half g_wtOM[NCHUNK * 1024];             // fp16 fragment-ordered offmask B tiles (147 KB)
__device__ float  g_offmask[BATCH * HH * WW * 32];   // 18 off, 9 mask per pixel (fp32)

// ---------------- helpers ----------------
__device__ __forceinline__ uint32_t smem_u32(const void* p) {
    uint32_t a;
    asm("{ .reg .u64 t; cvta.to.shared.u64 t, %1; cvt.u32.u64 %0, t; }" : "=r"(a) : "l"(p));
    return a;
}
__device__ __forceinline__ void cp_async16(uint32_t s, const void* g) {
    asm volatile("cp.async.cg.shared.global [%0], [%1], 16;" :: "r"(s), "l"(g) : "memory");
}
__device__ __forceinline__ void cp_commit() { asm volatile("cp.async.commit_group;" ::: "memory"); }
__device__ __forceinline__ void cp_wait0()  { asm volatile("cp.async.wait_group 0;" ::: "memory"); }

__device__ __forceinline__ void mma_f16(float4& d, const uint4& a, const uint2& b) {
    asm volatile(
        "mma.sync.aligned.m16n8k16.row.col.f32.f16.f16.f32 "
        "{%0,%1,%2,%3}, {%4,%5,%6,%7}, {%8,%9}, {%0,%1,%2,%3};"
        : "+f"(d.x), "+f"(d.y), "+f"(d.z), "+f"(d.w)
        : "r"(a.x), "r"(a.y), "r"(a.z), "r"(a.w), "r"(b.x), "r"(b.y));
}

// ---------------- kernel 1: NCHW fp32 -> NHWC fp16 transpose ----------------
__global__ void transpose_x_kernel(const float* __restrict__ x)
{
    __shared__ float tile[32][33];
    int bh = blockIdx.z;
    int b = bh >> 6, h = bh & 63;
    int wbase = blockIdx.x * 32;
    int cbase = blockIdx.y * 32;
    int tx = threadIdx.x, ty = threadIdx.y;

    int wi = wbase + tx;
#pragma unroll
    for (int j = 0; j < 4; j++) {
        int c = cbase + ty + j * 8;
        tile[ty + j * 8][tx] = x[((b * CIN + c) * HH + h) * WW + wi];
    }
    __syncthreads();
    int c2 = cbase + tx;
#pragma unroll
    for (int j = 0; j < 4; j++) {
        int w2 = wbase + ty + j * 8;
        float v = tile[tx][ty + j * 8];
        g_xh[((bh) * WW + w2) * CIN + c2] = __float2half_rn(v);
    }
}

// ---------------- kernel 2: pack main weight into fp16 fragment-ordered B tiles ----------------
__global__ void pack_wtB_kernel(const float* __restrict__ weight)
{
    int i = blockIdx.x * blockDim.x + threadIdx.x;
    if (i >= NCHUNK * 4096) return;
    int q = i >> 12;
    int w = i & 4095;
    int r = w & 1;
    int lane = (w >> 1) & 31;
    int ks = (w >> 6) & 1;
    int n_blk = (w >> 7) & 31;
    int tap = q >> 3;
    int n = n_blk * 8 + (lane >> 2);
    int c = (q & 7) * 32 + ks * 16 + (lane & 3) * 2 + r * 8;
    float v0 = weight[(n * CIN + c) * K2 + tap];
    float v1 = weight[(n * CIN + c + 1) * K2 + tap];
    ((__half2*)g_wtB)[i] = __floats2half2_rn(v0, v1);
}

// ---------------- kernel 2b: pack offset+mask weights into fp16 B tiles (N=32 padded) ----------------
__global__ void pack_wtOM_kernel(const float* __restrict__ offset_w,
                                 const float* __restrict__ mod_w)
{
    int i = blockIdx.x * blockDim.x + threadIdx.x;
    if (i >= NCHUNK * 512) return;
    int q = i >> 9;
    int w = i & 511;
    int r = w & 1;
    int lane = (w >> 1) & 31;
    int ks = (w >> 6) & 1;
    int n_blk = (w >> 7) & 3;
    int tap = q >> 3;
    int n = n_blk * 8 + (lane >> 2);
    int c = (q & 7) * 32 + ks * 16 + (lane & 3) * 2 + r * 8;
    float v0 = 0.f, v1 = 0.f;
    if (n < 18)      { v0 = offset_w[(n * CIN + c) * K2 + tap]; v1 = offset_w[(n * CIN + c + 1) * K2 + tap]; }
    else if (n < 27) { v0 = mod_w[((n - 18) * CIN + c) * K2 + tap]; v1 = mod_w[((n - 18) * CIN + c + 1) * K2 + tap]; }
    ((__half2*)g_wtOM)[i] = __floats2half2_rn(v0, v1);
}

// ---------------- kernel 3: offset/mask conv via fp16 mma — M=128 (2 rows), 4M x 2N warps ----------------
// Block = 2 rows: M=128 px, N=32, K=2304 in 72 chunks. 256 threads = 8 warps.
// Per warp: 2 m_blks x 2 n x 2 ks = 8 MMAs per chunk. Distance-2 A pipeline, ga[2] only.
__global__ __launch_bounds__(256) void offmask_mma_kernel(const float* __restrict__ offset_b,
                                                          const float* __restrict__ mod_b)
{
    __shared__ __align__(16) char smA[2][8192];   // A frag: [m_blk8][ks16 2][lane32][16B]
    __shared__ __align__(16) char smB[2][2048];   // B frag: [n_blk4][ks16 2][lane32][8B]

    int t = threadIdx.x;
    int wid = t >> 5, lane = t & 31;
    int bid = blockIdx.x;
    int b = bid >> 5, h0 = (bid & 31) << 1;

    uint32_t sbB[2] = { smem_u32(smB[0]), smem_u32(smB[1]) };

    // staging identity: pixel p_ = t>>1 (0..127), half = t&1 -> 16 channels of the 32-chunk
    int p_ = t >> 1, half = t & 1;
    int m_blk = p_ >> 4, rr = p_ & 15, rA = rr & 7, r8 = rr >> 3;

    int wm = wid & 3, wn = wid >> 2;

    float4 acc[2][2];
#pragma unroll
    for (int mi = 0; mi < 2; mi++)
#pragma unroll
        for (int ni = 0; ni < 2; ni++) acc[mi][ni] = make_float4(0.f, 0.f, 0.f, 0.f);

    uint4 ga[2];   // 16 fp16 channels — loaded one FULL iteration before STS

    auto loadA = [&](int q) {
        int tap = q >> 3;
        int ki = tap / 3, kj = tap - ki * 3;
        int y = h0 + (p_ >> 6) + ki - 1;
        int xc = (p_ & 63) + kj - 1;
        if ((unsigned)y < 64u && (unsigned)xc < 64u) {
            const uint4* src = (const uint4*)&g_xh[(((b * HH + y) * WW + xc) * CIN) + (q & 7) * 32 + half * 16];
            ga[0] = src[0];
            ga[1] = src[1];
        } else {
            ga[0] = make_uint4(0, 0, 0, 0);
            ga[1] = make_uint4(0, 0, 0, 0);
        }
    };
    // thread covers q4 = half*2 + g, g in {0,1}: channels q4*8..+7
    auto stsA = [&](int buf) {
        __half2* Aw = (__half2*)smA[buf];
#pragma unroll
        for (int g = 0; g < 2; g++) {
            int base = ((m_blk * 2 + half) * 32 + 4 * rA) * 4 + r8 + 2 * g;
            const __half2* v = (const __half2*)&ga[g];
            Aw[base + 0 * 4] = v[0];
            Aw[base + 1 * 4] = v[1];
            Aw[base + 2 * 4] = v[2];
            Aw[base + 3 * 4] = v[3];
        }
    };

    // prologue: stage chunk 0 into buffer 0; preload chunk 1 into registers
    loadA(0);
    stsA(0);
    loadA(1);
    if (t < 128) cp_async16(sbB[0] + t * 16, (const char*)g_wtOM + t * 16);
    cp_commit();
    cp_wait0();
    __syncthreads();

    for (int q = 0; q < NCHUNK; q++) {
        int buf = q & 1, nbuf = buf ^ 1;
        bool pre = (q + 1 < NCHUNK);
        if (pre) {
            if (t < 128) cp_async16(sbB[nbuf] + t * 16, (const char*)g_wtOM + (size_t)(q + 1) * 2048 + t * 16);
            cp_commit();
        }

        const uint4* As = (const uint4*)smA[buf];
        const uint2* Bs = (const uint2*)smB[buf];
#pragma unroll
        for (int ks = 0; ks < 2; ks++) {
            uint4 a0 = As[((wm * 2 + 0) * 2 + ks) * 32 + lane];
            uint4 a1 = As[((wm * 2 + 1) * 2 + ks) * 32 + lane];
#pragma unroll
            for (int ni = 0; ni < 2; ni++) {
                uint2 bf = Bs[((wn * 2 + ni) * 2 + ks) * 32 + lane];
                mma_f16(acc[0][ni], a0, bf);
                mma_f16(acc[1][ni], a1, bf);
            }
        }

        if (pre) stsA(nbuf);               // ga holds chunk q+1 (loaded at iter q-1) — no stall
        if (q + 2 < NCHUNK) loadA(q + 2);  // refill ga for next iteration
        cp_wait0();
        __syncthreads();
    }

    // epilogue: bias + sigmoid(mask), store fp32
#pragma unroll
    for (int mi = 0; mi < 2; mi++) {
        int mt = wm * 2 + mi;
#pragma unroll
        for (int ni = 0; ni < 2; ni++) {
            const float* a4 = (const float*)&acc[mi][ni];
            int nb = wn * 16 + ni * 8 + (lane & 3) * 2;
#pragma unroll
            for (int rr2 = 0; rr2 < 2; rr2++) {
                int px = mt * 16 + (lane >> 2) + rr2 * 8;
                int h = h0 + (px >> 6), w = px & 63;
#pragma unroll
                for (int cc = 0; cc < 2; cc++) {
                    int n = nb + cc;
                    if (n >= 27) continue;
                    float v = a4[rr2 * 2 + cc];
                    if (n < 18) v += offset_b[n];
                    else        v = 2.f / (1.f + expf(-(v + mod_b[n - 18])));
                    g_offmask[(((b * HH + h) * WW) + w) * 32 + n] = v;
                }
            }
        }
    }
}

// ---------------- kernel 4: deformable conv via fp16 mma (R13 distance-1 staging) ----------------
// Block = 2 rows: M=128 px, N=256, K=2304 in 72 chunks of 32. 512 threads = 16 warps (4M x 4N).
#define SM_MIDX   0
#define SM_MWGT   18432
#define SM_A0     36864
#define SM_A1     45056
#define SM_B0     53248
#define SM_B1     69632
#define SM_BIAS   86016
#define SM_TOTAL  87040

__global__ __launch_bounds__(512) void deform_mma_kernel(const float* __restrict__ bias,
                                                         float* __restrict__ out)
{
    extern __shared__ char smem[];
    uint32_t sb = smem_u32(smem);
    int t = threadIdx.x;
    int bid = blockIdx.x;
    int b = bid >> 5, h0 = (bid & 31) << 1;

    int4*   midx  = (int4*)(smem + SM_MIDX);
    float4* mwgt  = (float4*)(smem + SM_MWGT);
    float*  biasS = (float*)(smem + SM_BIAS);

    if (t < 256) biasS[t] = bias[t];

    // ---- per-block sampling metadata: 128 px x 9 taps ----
    for (int e = t; e < 128 * K2; e += 512) {
        int p = e / K2;
        int k = e - p * K2;
        int r = p >> 6, w = p & 63;
        int h = h0 + r;
        const float* om = &g_offmask[(((b * HH + h) * WW) + w) * 32];
        float dy = om[2 * k];
        float dx = om[2 * k + 1];
        float m  = om[18 + k];
        int ki = k / 3, kj = k - ki * 3;
        float py = dy + (float)(h - 1 + ki);
        float px = dx + (float)(w - 1 + kj);
        float y0f = floorf(py), x0f = floorf(px);
        float ly = py - y0f, lx = px - x0f;
        int y0 = (int)y0f, x0 = (int)x0f;
        int y1 = y0 + 1, x1 = x0 + 1;
        float wy0 = 1.f - ly, wx0 = 1.f - lx;
        bool vy0 = (y0 >= 0) && (y0 < HH);
        bool vy1 = (y1 >= 0) && (y1 < HH);
        bool vx0 = (x0 >= 0) && (x0 < WW);
        bool vx1 = (x1 >= 0) && (x1 < WW);
        float w00 = (vy0 && vx0) ? wy0 * wx0 * m : 0.f;
        float w01 = (vy0 && vx1) ? wy0 * lx  * m : 0.f;
        float w10 = (vy1 && vx0) ? ly  * wx0 * m : 0.f;
        float w11 = (vy1 && vx1) ? ly  * lx  * m : 0.f;
        int y0c = min(max(y0, 0), HH - 1);
        int y1c = min(max(y1, 0), HH - 1);
        int x0c = min(max(x0, 0), WW - 1);
        int x1c = min(max(x1, 0), WW - 1);
        midx[e] = make_int4(((b * HH + y0c) * WW + x0c) * CIN,
                            ((b * HH + y0c) * WW + x1c) * CIN,
                            ((b * HH + y1c) * WW + x0c) * CIN,
                            ((b * HH + y1c) * WW + x1c) * CIN);
        mwgt[e] = make_float4(w00, w01, w10, w11);
    }
    __syncthreads();

    // staging identity: pixel p_=t>>2, channels q4*8..+7 of chunk
    int p_ = t >> 2, q4 = t & 3;
    int m_blk = p_ >> 4, rr = p_ & 15, rA = rr & 7, r8 = rr >> 3;
    int jw = r8 + 2 * (q4 & 1);
    int ks16s = q4 >> 1;
    int stsBase = ((m_blk * 2 + ks16s) * 32 + 4 * rA) * 4 + jw;   // half2-word index in A tile

    int wid = t >> 5, lane = t & 31;
    int wm = wid & 3, wn = wid >> 2;

    float4 acc[2][8];
#pragma unroll
    for (int mi = 0; mi < 2; mi++)
#pragma unroll
        for (int ni = 0; ni < 8; ni++) acc[mi][ni] = make_float4(0.f, 0.f, 0.f, 0.f);

    char* Abuf[2] = { smem + SM_A0, smem + SM_A1 };
    char* Bbuf[2] = { smem + SM_B0, smem + SM_B1 };
    uint32_t BbufU[2] = { sb + SM_B0, sb + SM_B1 };

    uint4 c00, c01, c10, c11;   // 4 corners x 8 fp16 channels
    int4 id;                    // corner base indices — persist across the 8 c-chunks of a tap
    float4 wg;                  // corner weights — same

    auto loadCorners = [&](int qq) {
        int cb = ((qq & 7) << 5) + q4 * 8;
        c00 = *(const uint4*)&g_xh[id.x + cb];
        c01 = *(const uint4*)&g_xh[id.y + cb];
        c10 = *(const uint4*)&g_xh[id.z + cb];
        c11 = *(const uint4*)&g_xh[id.w + cb];
    };
    auto stsA = [&](int buf) {
        __half2* Aw = (__half2*)Abuf[buf];
        const __half2* a0 = (const __half2*)&c00;
        const __half2* a1 = (const __half2*)&c01;
        const __half2* a2 = (const __half2*)&c10;
        const __half2* a3 = (const __half2*)&c11;
#pragma unroll
        for (int ci = 0; ci < 4; ci++) {
            float2 f0 = __half22float2(a0[ci]);
            float2 f1 = __half22float2(a1[ci]);
            float2 f2 = __half22float2(a2[ci]);
            float2 f3 = __half22float2(a3[ci]);
            float sx = wg.x * f0.x + wg.y * f1.x + wg.z * f2.x + wg.w * f3.x;
            float sy = wg.x * f0.y + wg.y * f1.y + wg.z * f2.y + wg.w * f3.y;
            Aw[stsBase + ci * 4] = __floats2half2_rn(sx, sy);
        }
    };

    // prologue: stage chunk 0 (tap 0)
    {
        id = midx[p_ * K2 + 0];
        wg = mwgt[p_ * K2 + 0];
        loadCorners(0);
#pragma unroll
        for (int i = 0; i < 2; i++)
            cp_async16(BbufU[0] + t * 16 + i * 8192, (const char*)g_wtB + t * 16 + i * 8192);
        cp_commit();
        stsA(0);
        cp_wait0();
        __syncthreads();
    }

    for (int q = 0; q < NCHUNK; q++) {
        int buf = q & 1, nbuf = buf ^ 1;
        bool pre = (q + 1 < NCHUNK);

        if (pre) {
            int qq = q + 1;
            if ((qq & 7) == 0) {            // tap boundary: refresh metadata
                int tap = qq >> 3;
                id = midx[p_ * K2 + tap];
                wg = mwgt[p_ * K2 + tap];
            }
            loadCorners(qq);
            const char* bsrc = (const char*)g_wtB + (size_t)qq * 16384;
#pragma unroll
            for (int i = 0; i < 2; i++)
                cp_async16(BbufU[nbuf] + t * 16 + i * 8192, bsrc + t * 16 + i * 8192);
            cp_commit();
        }

        const uint4* As = (const uint4*)Abuf[buf];
        const uint2* Bs = (const uint2*)Bbuf[buf];

        // ks = 0
        {
            uint4 a0 = As[((wm * 2 + 0) * 2 + 0) * 32 + lane];
            uint4 a1 = As[((wm * 2 + 1) * 2 + 0) * 32 + lane];
#pragma unroll
            for (int ni = 0; ni < 8; ni++) {
                uint2 bf = Bs[((wn * 8 + ni) * 2 + 0) * 32 + lane];
                mma_f16(acc[0][ni], a0, bf);
                mma_f16(acc[1][ni], a1, bf);
            }
        }

        // convert + STS A for q+1 (overlap with MMA)
        if (pre) stsA(nbuf);

        // ks = 1
        {
            uint4 a0 = As[((wm * 2 + 0) * 2 + 1) * 32 + lane];
            uint4 a1 = As[((wm * 2 + 1) * 2 + 1) * 32 + lane];
#pragma unroll
            for (int ni = 0; ni < 8; ni++) {
                uint2 bf = Bs[((wn * 8 + ni) * 2 + 1) * 32 + lane];
                mma_f16(acc[0][ni], a0, bf);
                mma_f16(acc[1][ni], a1, bf);
            }
        }

        cp_wait0();
        __syncthreads();
    }

    // ---- epilogue: bias + scattered NCHW stores ----
    int gid = lane >> 2, tig = lane & 3;
#pragma unroll
    for (int mi = 0; mi < 2; mi++) {
        int p0 = wm * 32 + mi * 16 + gid;
        int p1 = p0 + 8;
        int h_0 = h0 + (p0 >> 6), w_0 = p0 & 63;
        int h_1 = h0 + (p1 >> 6), w_1 = p1 & 63;
#pragma unroll
        for (int ni = 0; ni < 8; ni++) {
            int o0 = wn * 64 + ni * 8 + tig * 2;
            int o1 = o0 + 1;
            float4 d = acc[mi][ni];
            out[((b * COUT + o0) * HH + h_0) * WW + w_0] = d.x + biasS[o0];
            out[((b * COUT + o1) * HH + h_0) * WW + w_0] = d.y + biasS[o1];
            out[((b * COUT + o0) * HH + h_1) * WW + w_1] = d.z + biasS[o0];
            out[((b * COUT + o1) * HH + h_1) * WW + w_1] = d.w + biasS[o1];
        }
    }
}

// ---------------- launcher ----------------
extern "C" void kernel_launch(void* const* d_in, const int* in_sizes, int n_in,
                              void* d_out, int out_size)
{
    const float* x        = (const float*)d_in[0];
    const float* offset_w = (const float*)d_in[1];
    const float* offset_b = (const float*)d_in[2];
    const float* mod_w    = (const float*)d_in[3];
    const float* mod_b    = (const float*)d_in[4];
    const float* weight   = (const float*)d_in[5];
    const float* bias     = (const float*)d_in[6];
    float* out = (float*)d_out;

    cudaFuncSetAttribute(deform_mma_kernel, cudaFuncAttributeMaxDynamicSharedMemorySize, SM_TOTAL);

    transpose_x_kernel<<<dim3(2, 8, BATCH * HH), dim3(32, 8)>>>(x);
    pack_wtB_kernel<<<(NCHUNK * 4096 + 255) / 256, 256>>>(weight);
    pack_wtOM_kernel<<<(NCHUNK * 512 + 255) / 256, 256>>>(offset_w, mod_w);
    offmask_mma_kernel<<<BATCH * HH / 2, 256>>>(offset_b, mod_b);
    deform_mma_kernel<<<BATCH * HH / 2, 512, SM_TOTAL>>>(bias, out);
}